// round 1
// baseline (speedup 1.0000x reference)
#include <cuda_runtime.h>

#define SLEN 1024
#define BATCH 256
#define DIN 64
#define HID 128

// per-direction fc contributions: [dir][b][t]
__device__ float g_contrib[2 * BATCH * SLEN];

typedef unsigned long long u64;

__device__ __forceinline__ u64 pack2(float lo, float hi) {
    u64 r; asm("mov.b64 %0, {%1, %2};" : "=l"(r) : "f"(lo), "f"(hi)); return r;
}
__device__ __forceinline__ void fma2(u64 &d, u64 a, u64 b) {
    asm("fma.rn.f32x2 %0, %1, %2, %0;" : "+l"(d) : "l"(a), "l"(b));
}
__device__ __forceinline__ float sum2(u64 v) {
    float lo, hi; asm("mov.b64 {%0, %1}, %2;" : "=f"(lo), "=f"(hi) : "l"(v));
    return lo + hi;
}
// tanh(x) = 1 - 2/(exp2(2*log2(e)*x) + 1); ex2/rcp approx err ~1e-7, safe for fp32 path
__device__ __forceinline__ float fast_tanh(float x) {
    float e, r;
    asm("ex2.approx.f32 %0, %1;" : "=f"(e) : "f"(x * 2.8853900817779268f));
    asm("rcp.approx.f32 %0, %1;" : "=f"(r) : "f"(e + 1.0f));
    return fmaf(-2.0f, r, 1.0f);
}

__global__ __launch_bounds__(256, 1)
void birnn_recur_kernel(const float* __restrict__ inputs,
                        const float* __restrict__ Wih_fw, const float* __restrict__ Whh_fw,
                        const float* __restrict__ bih_fw, const float* __restrict__ bhh_fw,
                        const float* __restrict__ Wih_bw, const float* __restrict__ Whh_bw,
                        const float* __restrict__ bih_bw, const float* __restrict__ bhh_bw,
                        const float* __restrict__ fcW)
{
    __shared__ float stage[8192];                       // 32 KB weight staging
    __shared__ __align__(16) float kbuf[4][192];        // [batch][h(128) | x(64)]
    __shared__ float red[8][2];

    const int tid  = threadIdx.x;
    const int j    = tid & 127;      // output unit
    const int half = tid >> 7;       // which batch pair (0: b0,b1 ; 1: b2,b3)
    const int dir  = blockIdx.x >> 6;
    const int grp  = blockIdx.x & 63;
    const int bb   = grp * 4;        // batch base
    const int bl   = tid >> 6;       // batch lane for x loads (0..3)
    const int dl   = tid & 63;       // d index for x loads
    const int lane = tid & 31;
    const int wid  = tid >> 5;

    const float* Wih = dir ? Wih_bw : Wih_fw;
    const float* Whh = dir ? Whh_bw : Whh_fw;
    const float* bih = dir ? bih_bw : bih_fw;
    const float* bhh = dir ? bhh_bw : bhh_fw;

    // ---- load combined weight row [Whh[j][0:128] | Wih[j][0:64]] into registers ----
    u64 w2[96];

    for (int i = tid; i < 64 * HID; i += 256) stage[i] = Whh[i];
    __syncthreads();
    if (j < 64) {
        const ulonglong2* src = (const ulonglong2*)(stage + j * HID);
        #pragma unroll
        for (int q = 0; q < 32; ++q) { ulonglong2 v = src[q]; w2[2*q] = v.x; w2[2*q+1] = v.y; }
    }
    __syncthreads();
    for (int i = tid; i < 64 * HID; i += 256) stage[i] = Whh[64 * HID + i];
    __syncthreads();
    if (j >= 64) {
        const ulonglong2* src = (const ulonglong2*)(stage + (j - 64) * HID);
        #pragma unroll
        for (int q = 0; q < 32; ++q) { ulonglong2 v = src[q]; w2[2*q] = v.x; w2[2*q+1] = v.y; }
    }
    __syncthreads();
    for (int i = tid; i < HID * DIN; i += 256) stage[i] = Wih[i];
    __syncthreads();
    {
        const ulonglong2* src = (const ulonglong2*)(stage + j * DIN);
        #pragma unroll
        for (int q = 0; q < 16; ++q) { ulonglong2 v = src[q]; w2[64+2*q] = v.x; w2[64+2*q+1] = v.y; }
    }

    const float bias_j = bih[j] + bhh[j];
    const float fcw_j  = fcW[dir * HID + j];

    // ---- init state: h=0, x=x_{t0} ----
    for (int i = tid; i < 4 * 192; i += 256) (&kbuf[0][0])[i] = 0.0f;
    const int t0 = dir ? (SLEN - 1) : 0;
    float x_first = inputs[(bb + bl) * (SLEN * DIN) + t0 * DIN + dl];
    __syncthreads();
    kbuf[bl][HID + dl] = x_first;
    __syncthreads();

    const float* kb0 = &kbuf[half * 2][0];
    const float* kb1 = &kbuf[half * 2 + 1][0];

    for (int step = 0; step < SLEN; ++step) {
        const int t = dir ? (SLEN - 1 - step) : step;

        // prefetch next timestep's x (latency hidden under the FMA loop)
        float xn = 0.0f;
        if (step + 1 < SLEN) {
            const int tn = dir ? (SLEN - 2 - step) : (step + 1);
            xn = __ldg(&inputs[(bb + bl) * (SLEN * DIN) + tn * DIN + dl]);
        }

        // pre-activation: bias + sum_k state[k] * w[j][k]  (K = 192, f32x2 packed)
        u64 aP0 = pack2(bias_j, 0.0f), aQ0 = 0ull;
        u64 aP1 = pack2(bias_j, 0.0f), aQ1 = 0ull;
        #pragma unroll
        for (int q = 0; q < 48; ++q) {
            ulonglong2 h0 = *(const ulonglong2*)(kb0 + q * 4);
            ulonglong2 h1 = *(const ulonglong2*)(kb1 + q * 4);
            fma2(aP0, h0.x, w2[2*q]);
            fma2(aP1, h1.x, w2[2*q]);
            fma2(aQ0, h0.y, w2[2*q+1]);
            fma2(aQ1, h1.y, w2[2*q+1]);
        }
        float v0 = fast_tanh(sum2(aP0) + sum2(aQ0));
        float v1 = fast_tanh(sum2(aP1) + sum2(aQ1));

        __syncthreads();   // all reads of kbuf for step t are done

        kbuf[half * 2][j]     = v0;     // h_{t+1}
        kbuf[half * 2 + 1][j] = v1;
        kbuf[bl][HID + dl]    = xn;     // x for next step

        // fused fc head: reduce v * fc_W over j
        float s0 = v0 * fcw_j;
        float s1 = v1 * fcw_j;
        #pragma unroll
        for (int m = 16; m > 0; m >>= 1) {
            s0 += __shfl_xor_sync(0xffffffffu, s0, m);
            s1 += __shfl_xor_sync(0xffffffffu, s1, m);
        }
        if (lane == 0) { red[wid][0] = s0; red[wid][1] = s1; }

        __syncthreads();   // h/x/red visible

        if (tid < 4) {
            const int wb = (tid >> 1) * 4;   // batches 0,1 <- warps 0..3 ; 2,3 <- warps 4..7
            const int f  = tid & 1;
            float c = red[wb][f] + red[wb+1][f] + red[wb+2][f] + red[wb+3][f];
            g_contrib[(dir * BATCH + bb + tid) * SLEN + t] = c;
        }
    }
}

__global__ void birnn_finalize_kernel(const float* __restrict__ fcb, float* __restrict__ out)
{
    int i = blockIdx.x * blockDim.x + threadIdx.x;
    if (i < BATCH * SLEN)
        out[i] = g_contrib[i] + g_contrib[BATCH * SLEN + i] + fcb[0];
}

extern "C" void kernel_launch(void* const* d_in, const int* in_sizes, int n_in,
                              void* d_out, int out_size)
{
    (void)in_sizes; (void)n_in;
    const float* inputs = (const float*)d_in[0];
    const float* Wih_fw = (const float*)d_in[1];
    const float* Whh_fw = (const float*)d_in[2];
    const float* bih_fw = (const float*)d_in[3];
    const float* bhh_fw = (const float*)d_in[4];
    const float* Wih_bw = (const float*)d_in[5];
    const float* Whh_bw = (const float*)d_in[6];
    const float* bih_bw = (const float*)d_in[7];
    const float* bhh_bw = (const float*)d_in[8];
    const float* fcW    = (const float*)d_in[9];
    const float* fcb    = (const float*)d_in[10];
    float* out = (float*)d_out;

    birnn_recur_kernel<<<128, 256>>>(inputs,
                                     Wih_fw, Whh_fw, bih_fw, bhh_fw,
                                     Wih_bw, Whh_bw, bih_bw, bhh_bw,
                                     fcW);
    birnn_finalize_kernel<<<(BATCH * SLEN + 255) / 256, 256>>>(fcb, out);
    (void)out_size;
}